// round 15
// baseline (speedup 1.0000x reference)
#include <cuda_runtime.h>
#include <math.h>

typedef unsigned long long ull;

#define NBC  6          // B*C
#define NBLK 768        // 128 blocks per bc; block = 8x8x4 L2 cells (half an L5 cell)

// Static __device__ scratch (allocation-free). Zero-init; finalize resets for replay.
__device__ double       g_acc[NBC][45];       // L0..L4 stats
__device__ float        g_l5h[NBC][64][2];    // half-sums of the 64 L5 cells per bc
__device__ unsigned int g_ctr;

// ---- packed f32x2 helpers (Blackwell 2xFP32; ptxas won't auto-emit) ----
__device__ __forceinline__ ull pk2(float lo, float hi) {
    ull r; asm("mov.b64 %0, {%1, %2};" : "=l"(r) : "f"(lo), "f"(hi)); return r;
}
__device__ __forceinline__ float2 upk2(ull v) {
    float2 f; asm("mov.b64 {%0, %1}, %2;" : "=f"(f.x), "=f"(f.y) : "l"(v)); return f;
}
__device__ __forceinline__ ull add2(ull a, ull b) {
    ull r; asm("add.rn.f32x2 %0, %1, %2;" : "=l"(r) : "l"(a), "l"(b)); return r;
}
__device__ __forceinline__ ull mul2(ull a, ull b) {
    ull r; asm("mul.rn.f32x2 %0, %1, %2;" : "=l"(r) : "l"(a), "l"(b)); return r;
}
__device__ __forceinline__ ull fma2(ull a, ull b, ull c) {
    ull r; asm("fma.rn.f32x2 %0, %1, %2, %3;" : "=l"(r) : "l"(a), "l"(b), "l"(c)); return r;
}
__device__ __forceinline__ float rcpa(float x) {
    float r; asm("rcp.approx.f32 %0, %1;" : "=f"(r) : "f"(x)); return r;
}
__device__ __forceinline__ float lg2a(float x) {
    float r; asm("lg2.approx.f32 %0, %1;" : "=f"(r) : "f"(x)); return r;
}
__device__ __forceinline__ ulonglong2 ld2(const float* p) {
    return *reinterpret_cast<const ulonglong2*>(p);
}

// Packed pair accumulation, both values nonzero. 3 MUFU via rcp-of-product trick.
__device__ __forceinline__ void acc_pair_t(ull x, ull& S2, ull& S3, ull& S4,
                                           ull& S5, float& Sm1, float& Sm2,
                                           float& T2a, float& T2b) {
    float2 f = upk2(x);
    float r  = rcpa(f.x * f.y);             // MUFU.RCP
    float la = lg2a(f.x), lb = lg2a(f.y);   // 2x MUFU.LG2
    ull xx = mul2(x, x);
    S2 = add2(S2, xx);
    ull x3 = mul2(xx, x);
    S3 = add2(S3, x3);
    S4 = fma2(xx, xx, S4);
    S5 = fma2(x3, xx, S5);
    float2 fx = upk2(xx);
    Sm1 = fmaf(f.x + f.y, r, Sm1);
    Sm2 = fmaf(fx.x + fx.y, r * r, Sm2);
    T2a = fmaf(f.x, la, T2a);
    T2b = fmaf(f.y, lb, T2b);
}

// Scalar zero-skipping accumulation (rare slow path).
__device__ __forceinline__ void acc_one(float v, ull& S2, ull& S3, ull& S4,
                                        ull& S5, float& Sm1, float& Sm2, float& T2a,
                                        float& cnt) {
    if (v != 0.0f) {
        float inv = rcpa(v), lg = lg2a(v);
        float v2 = v * v, v3 = v2 * v;
        S2 = add2(S2, pk2(v2, 0.f));
        S3 = add2(S3, pk2(v3, 0.f));
        S4 = add2(S4, pk2(v2 * v2, 0.f));
        S5 = add2(S5, pk2(v3 * v2, 0.f));
        Sm1 += inv;
        Sm2 += inv * inv;
        T2a = fmaf(v, lg, T2a);
        cnt += 1.0f;
    }
}

// Stats WITHOUT stat0 (S1 redundant at L1..L4; derived from L5 sums).
__device__ __forceinline__ void acc_scalar8(float v, float* st) {
    if (v != 0.0f) {
        float inv = rcpa(v), lg = lg2a(v);
        float v2 = v * v, v3 = v2 * v;
        st[1] += v2;  st[2] += v3;
        st[3] += v2 * v2;  st[4] += v3 * v2;
        st[5] += inv;  st[6] += inv * inv;
        st[7] += v * lg;  st[8] += 1.0f;
    }
}

// Full 9-stat version (finalize L5 only).
__device__ __forceinline__ void acc_scalar9(float v, float* st) {
    if (v != 0.0f) {
        float inv = rcpa(v), lg = lg2a(v);
        float v2 = v * v, v3 = v2 * v;
        st[0] += v;
        st[1] += v2;  st[2] += v3;
        st[3] += v2 * v2;  st[4] += v3 * v2;
        st[5] += inv;  st[6] += inv * inv;
        st[7] += v * lg;  st[8] += 1.0f;
    }
}

__device__ __forceinline__ float wred32(float v) {
#pragma unroll
    for (int o = 16; o; o >>= 1) v += __shfl_down_sync(0xFFFFFFFFu, v, o);
    return v;
}

// L0 stats of one plane (4 rows x 4 floats).
__device__ __forceinline__ void plane_stats(ulonglong2 A0, ulonglong2 A1,
                                            ulonglong2 A2, ulonglong2 A3,
                                            ull& S2, ull& S3, ull& S4, ull& S5,
                                            float& Sm1, float& Sm2, float& T2a,
                                            float& T2b, float& cnt) {
    ull pr = mul2(mul2(mul2(A0.x, A0.y), mul2(A1.x, A1.y)),
                  mul2(mul2(A2.x, A2.y), mul2(A3.x, A3.y)));
    float2 pf = upk2(pr);
    if (pf.x * pf.y != 0.0f) {
        acc_pair_t(A0.x, S2, S3, S4, S5, Sm1, Sm2, T2a, T2b);
        acc_pair_t(A0.y, S2, S3, S4, S5, Sm1, Sm2, T2a, T2b);
        acc_pair_t(A1.x, S2, S3, S4, S5, Sm1, Sm2, T2a, T2b);
        acc_pair_t(A1.y, S2, S3, S4, S5, Sm1, Sm2, T2a, T2b);
        acc_pair_t(A2.x, S2, S3, S4, S5, Sm1, Sm2, T2a, T2b);
        acc_pair_t(A2.y, S2, S3, S4, S5, Sm1, Sm2, T2a, T2b);
        acc_pair_t(A3.x, S2, S3, S4, S5, Sm1, Sm2, T2a, T2b);
        acc_pair_t(A3.y, S2, S3, S4, S5, Sm1, Sm2, T2a, T2b);
        cnt += 16.0f;
    } else {
        ull us[8] = {A0.x, A0.y, A1.x, A1.y, A2.x, A2.y, A3.x, A3.y};
#pragma unroll 4
        for (int j = 0; j < 8; j++) {
            float2 vv = upk2(us[j]);
            acc_one(vv.x, S2, S3, S4, S5, Sm1, Sm2, T2a, cnt);
            acc_one(vv.y, S2, S3, S4, S5, Sm1, Sm2, T2a, cnt);
        }
    }
}

__global__ void __launch_bounds__(256, 4) fractal_kernel(const float* __restrict__ img,
                                                         const int* __restrict__ bounds,
                                                         float* __restrict__ out) {
    const int b   = blockIdx.x;
    const int tid = threadIdx.x;
    const int bc  = b >> 7, r = b & 127, tile = r >> 1, half = r & 1;
    const int tw = tile & 3, th = (tile >> 2) & 3, td = tile >> 4;
    const int cw = tid & 7, ch = (tid >> 3) & 7, cd = tid >> 6;   // cd 0..3

    __shared__ float l2s[256];
    __shared__ float l3s[32];
    __shared__ float w0[8][9], w1[8][9], w2[8][9];
    __shared__ float bs[45];
    __shared__ float accF[NBC][54];
    __shared__ unsigned int flag;

    ull S2 = 0, S3 = 0, S4 = 0, S5 = 0;
    float Sm1 = 0.f, Sm2 = 0.f, T2a = 0.f, T2b = 0.f, cnt = 0.f;
    float st1[9];
#pragma unroll
    for (int j = 0; j < 9; j++) st1[j] = 0.f;

    const float* base = img + ((size_t)bc << 21)
                      + (((size_t)(td << 3) + (half << 2) + cd) << 16)
                      + (((th << 3) + ch) << 9)
                      + (((tw << 3) + cw) << 2);

    // ---- pipelined 4-plane cell: load P0,P1; proc P0; load P2; proc P1(+octants);
    //      load P3; proc P2; proc P3(+octants) ----
    ulonglong2 A0, A1, A2, A3, B0, B1, B2, B3;
    ull r0, r1, r2, r3;
    float l2v = 0.f;

    A0 = ld2(base);          A1 = ld2(base + 128);
    A2 = ld2(base + 256);    A3 = ld2(base + 384);
    const float* p1 = base + 16384;
    B0 = ld2(p1);            B1 = ld2(p1 + 128);
    B2 = ld2(p1 + 256);      B3 = ld2(p1 + 384);

    plane_stats(A0, A1, A2, A3, S2, S3, S4, S5, Sm1, Sm2, T2a, T2b, cnt);
    r0 = add2(A0.x, A1.x); r1 = add2(A2.x, A3.x);
    r2 = add2(A0.y, A1.y); r3 = add2(A2.y, A3.y);

    const float* p2 = base + 32768;
    A0 = ld2(p2);            A1 = ld2(p2 + 128);
    A2 = ld2(p2 + 256);      A3 = ld2(p2 + 384);

    plane_stats(B0, B1, B2, B3, S2, S3, S4, S5, Sm1, Sm2, T2a, T2b, cnt);
    r0 = add2(r0, add2(B0.x, B1.x)); r1 = add2(r1, add2(B2.x, B3.x));
    r2 = add2(r2, add2(B0.y, B1.y)); r3 = add2(r3, add2(B2.y, B3.y));
    {   // octants of dz-pair 0
        float2 f0 = upk2(r0), f1 = upk2(r1), f2 = upk2(r2), f3 = upk2(r3);
        float l00 = f0.x + f0.y, l01 = f1.x + f1.y;
        float l10 = f2.x + f2.y, l11 = f3.x + f3.y;
        acc_scalar8(l00, st1); acc_scalar8(l01, st1);
        acc_scalar8(l10, st1); acc_scalar8(l11, st1);
        l2v += (l00 + l01) + (l10 + l11);
    }

    const float* p3 = base + 49152;
    B0 = ld2(p3);            B1 = ld2(p3 + 128);
    B2 = ld2(p3 + 256);      B3 = ld2(p3 + 384);

    plane_stats(A0, A1, A2, A3, S2, S3, S4, S5, Sm1, Sm2, T2a, T2b, cnt);
    r0 = add2(A0.x, A1.x); r1 = add2(A2.x, A3.x);
    r2 = add2(A0.y, A1.y); r3 = add2(A2.y, A3.y);

    plane_stats(B0, B1, B2, B3, S2, S3, S4, S5, Sm1, Sm2, T2a, T2b, cnt);
    r0 = add2(r0, add2(B0.x, B1.x)); r1 = add2(r1, add2(B2.x, B3.x));
    r2 = add2(r2, add2(B0.y, B1.y)); r3 = add2(r3, add2(B2.y, B3.y));
    {   // octants of dz-pair 1
        float2 f0 = upk2(r0), f1 = upk2(r1), f2 = upk2(r2), f3 = upk2(r3);
        float l00 = f0.x + f0.y, l01 = f1.x + f1.y;
        float l10 = f2.x + f2.y, l11 = f3.x + f3.y;
        acc_scalar8(l00, st1); acc_scalar8(l01, st1);
        acc_scalar8(l10, st1); acc_scalar8(l11, st1);
        l2v += (l00 + l01) + (l10 + l11);
    }

    // L2 stats (1 value per thread)
    float st2[9];
#pragma unroll
    for (int j = 0; j < 9; j++) st2[j] = 0.f;
    acc_scalar8(l2v, st2);

    l2s[tid] = l2v;           // layout (cd<<6)|(ch<<3)|cw == tid
    __syncthreads();

    // L3: 32 threads pool 2x2x2 from l2s (8x8x4 grid) -> l3s (4x4x2)
    float st3[9];
    if (tid < 32) {
#pragma unroll
        for (int j = 0; j < 9; j++) st3[j] = 0.f;
        int jw = tid & 3, jh = (tid >> 2) & 3, jd = tid >> 4;     // jd 0..1
        int b3 = (jd << 7) | (jh << 4) | (jw << 1);
        float l3v = 0.f;
#pragma unroll
        for (int di = 0; di < 2; di++)
#pragma unroll
            for (int hi = 0; hi < 2; hi++)
#pragma unroll
                for (int wi = 0; wi < 2; wi++)
                    l3v += l2s[b3 + (di << 6) + (hi << 3) + wi];
        acc_scalar8(l3v, st3);
        l3s[(jd << 4) | (jh << 2) | jw] = l3v;
    }
    __syncthreads();

    // L4: 4 threads pool 2x2x2 over l3s (4x4x2); half-L5 = sum of the 4 L4 values
    if (tid < 4) {
        int mw = tid & 1, mh = tid >> 1;
        int b4 = (mh << 3) | (mw << 1);       // jd base 0, spans both d-layers
        float l4v = 0.f;
#pragma unroll
        for (int di = 0; di < 2; di++)
#pragma unroll
            for (int hi = 0; hi < 2; hi++)
#pragma unroll
                for (int wi = 0; wi < 2; wi++)
                    l4v += l3s[(di << 4) + b4 + (hi << 2) + wi];
        float st4[9];
#pragma unroll
        for (int j = 0; j < 9; j++) st4[j] = 0.f;
        acc_scalar8(l4v, st4);
        float l5h = l4v;
#pragma unroll
        for (int o = 2; o; o >>= 1) {
            l5h += __shfl_down_sync(0xFu, l5h, o);
#pragma unroll
            for (int j = 0; j < 9; j++) st4[j] += __shfl_down_sync(0xFu, st4[j], o);
        }
        if (tid == 0) {
#pragma unroll
            for (int j = 0; j < 9; j++) bs[36 + j] = st4[j];     // L4
            g_l5h[bc][tile][half] = l5h;                          // half L5 cell sum
        }
    }

    // warp staging: L0/L1/L2 across 8 warps; L3 direct from warp-0 reduce
    {
        float st0[9];
        float2 f;
        st0[0] = 0.f;
        f = upk2(S2); st0[1] = f.x + f.y;
        f = upk2(S3); st0[2] = f.x + f.y;
        f = upk2(S4); st0[3] = f.x + f.y;
        f = upk2(S5); st0[4] = f.x + f.y;
        st0[5] = Sm1; st0[6] = Sm2; st0[7] = T2a + T2b; st0[8] = cnt;
        int lane = tid & 31, warp = tid >> 5;
#pragma unroll
        for (int j = 0; j < 9; j++) {
            float a0 = wred32(st0[j]);
            float a1 = wred32(st1[j]);
            float a2 = wred32(st2[j]);
            if (lane == 0) { w0[warp][j] = a0; w1[warp][j] = a1; w2[warp][j] = a2; }
        }
        if (tid < 32) {                       // warp 0 holds all L3 cells
#pragma unroll
            for (int j = 0; j < 9; j++) {
                float a3 = wred32(st3[j]);
                if (lane == 0) bs[27 + j] = a3;
            }
        }
    }
    __syncthreads();

    if (tid < 9) {
        float s = 0.f;
#pragma unroll
        for (int w = 0; w < 8; w++) s += w0[w][tid];
        bs[tid] = s;
    } else if (tid >= 32 && tid < 41) {
        int j = tid - 32;
        float s = 0.f;
#pragma unroll
        for (int w = 0; w < 8; w++) s += w1[w][j];
        bs[9 + j] = s;
    } else if (tid >= 64 && tid < 73) {
        int j = tid - 64;
        float s = 0.f;
#pragma unroll
        for (int w = 0; w < 8; w++) s += w2[w][j];
        bs[18 + j] = s;
    }
    __syncthreads();

    // global accumulate + arrival (store of g_l5h by tid0 fenced via tid0's path)
    if (tid < 45) {
        atomicAdd(&g_acc[bc][tid], (double)bs[tid]);
        __threadfence();
    }
    __syncthreads();
    if (tid == 0) flag = (atomicAdd(&g_ctr, 1u) == NBLK - 1) ? 1u : 0u;
    __syncthreads();
    if (!flag) return;
    if (tid == 0) __threadfence();
    __syncthreads();

    // ================= FINALIZE (last block) =================
    for (int u = tid; u < NBC * 45; u += 256)
        accF[u / 45][u % 45] = (float)g_acc[u / 45][u % 45];
    // L5 stats: warp w handles bc w (6 warps); lanes cover 64 cells in 2 strides
    if (tid < 192) {
        int fbc = tid >> 5, lane = tid & 31;
        float s5[9];
#pragma unroll
        for (int j = 0; j < 9; j++) s5[j] = 0.f;
#pragma unroll
        for (int ii = 0; ii < 2; ii++) {
            int i = lane + (ii << 5);
            float v = g_l5h[fbc][i][0] + g_l5h[fbc][i][1];
            acc_scalar9(v, s5);
        }
#pragma unroll
        for (int j = 0; j < 9; j++) {
            float s = wred32(s5[j]);
            if (lane == 0) accF[fbc][45 + j] = s;
        }
    }
    __syncthreads();

    // reset for next graph replay
    for (int u = tid; u < NBC * 45; u += 256) g_acc[u / 45][u % 45] = 0.0;
    if (tid == 0) g_ctr = 0;

    if (tid >= NBC * 8) return;
    int obc = tid >> 3;
    int k   = bounds[tid & 7];

    const float LN2 = 0.69314718055994531f;
    float bsum = accF[obc][45];             // L5 S1 = total image sum
    float lnb  = logf(bsum);

    float sp = 0.0f, spq = 0.0f;
    for (int s = 0; s < 6; s++) {
        const float* a = &accF[obc][s * 9];
        float pv;
        if (k == 1) {
            pv = (a[7] * LN2) / bsum - lnb;
        } else if (k == 0) {
            pv = logf(a[8]);
        } else {
            float S;
            switch (k) {
                case  2: S = a[1]; break;
                case  3: S = a[2]; break;
                case  4: S = a[3]; break;
                case  5: S = a[4]; break;
                case -1: S = a[5]; break;
                case -2: S = a[6]; break;
                default: S = __int_as_float(0x7FC00000); break;
            }
            pv = logf(S) - (float)k * lnb;
        }
        sp  += pv;
        spq += pv * ((float)s * LN2);
    }
    const float qs  = 15.0f * LN2;
    const float q2s = 55.0f * LN2 * LN2;
    const float den = 6.0f * q2s - qs * qs;
    float aa = (k == 1) ? 1.0f : 1.0f / (float)(k - 1);
    out[tid] = aa * (6.0f * spq - sp * qs) / den;
}

extern "C" void kernel_launch(void* const* d_in, const int* in_sizes, int n_in,
                              void* d_out, int out_size) {
    const float* img    = (const float*)d_in[0];
    const int*   bounds = (const int*)d_in[1];
    float*       out    = (float*)d_out;

    fractal_kernel<<<NBLK, 256>>>(img, bounds, out);
}